// round 1
// baseline (speedup 1.0000x reference)
#include <cuda_runtime.h>

// ---------------- scratch (device globals; no allocation allowed) -------------
__device__ float    g_wt[784 * 256];      // sign(w1)^T as fp32 +-1, layout [k][n]
__device__ unsigned g_h1[65536 * 8];      // packed sign bits of layer-1 output
__device__ unsigned g_w2p[128 * 8];       // packed sign(w2) rows (256 bits each)
__device__ unsigned g_w3p[32 * 4];        // packed sign(w3) rows (128 bits each)
__device__ unsigned g_w4p[16];            // packed sign(w4) rows (32 bits each)

// ---------------- prep: transpose + sign w1 -----------------------------------
__global__ void prep_w1t(const float* __restrict__ w1) {
    int i = blockIdx.x * blockDim.x + threadIdx.x;
    if (i < 784 * 256) {
        int k = i / 256, n = i % 256;
        g_wt[i] = (w1[n * 784 + k] >= 0.0f) ? 1.0f : -1.0f;
    }
}

// ---------------- prep: bit-pack w2/w3/w4 signs --------------------------------
__global__ void pack_w(const float* __restrict__ w2,
                       const float* __restrict__ w3,
                       const float* __restrict__ w4) {
    int t = blockIdx.x * blockDim.x + threadIdx.x;
    if (t < 128 * 8) {                       // w2: 128 rows x 8 words
        int r = t / 8, w = t % 8;
        unsigned v = 0;
        #pragma unroll
        for (int b = 0; b < 32; b++)
            v |= (w2[r * 256 + w * 32 + b] >= 0.0f) ? (1u << b) : 0u;
        g_w2p[t] = v;
    } else if (t < 128 * 8 + 32 * 4) {       // w3: 32 rows x 4 words
        int u = t - 1024;
        int r = u / 4, w = u % 4;
        unsigned v = 0;
        #pragma unroll
        for (int b = 0; b < 32; b++)
            v |= (w3[r * 128 + w * 32 + b] >= 0.0f) ? (1u << b) : 0u;
        g_w3p[u] = v;
    } else if (t < 1024 + 128 + 10) {        // w4: 10 rows x 1 word
        int r = t - 1152;
        unsigned v = 0;
        #pragma unroll
        for (int b = 0; b < 32; b++)
            v |= (w4[r * 32 + b] >= 0.0f) ? (1u << b) : 0u;
        g_w4p[r] = v;
    }
}

// ---------------- layer 1: fp32 SGEMM + sign + bitpack epilogue ----------------
// C[M,256] = x[M,784] @ g_wt[784,256]; emit packed sign bits to g_h1.
#define BM 128
#define BN 128
#define BK 16

__global__ __launch_bounds__(256) void l1_gemm(const float* __restrict__ x, int M) {
    __shared__ float smem[BK * BM + BK * BN];   // 16 KB: As[BK][BM] | Bs[BK][BN]
    float* As = smem;                 // transposed A tile: As[k][m]
    float* Bs = smem + BK * BM;       // Bs[k][n]

    const int tid = threadIdx.x;
    const int tx = tid % 16;          // column group
    const int ty = tid / 16;          // row group
    const int rowBase = blockIdx.x * BM;
    const int colBase = blockIdx.y * BN;
    const int K = 784;

    float acc[8][8];
    #pragma unroll
    for (int i = 0; i < 8; i++)
        #pragma unroll
        for (int j = 0; j < 8; j++) acc[i][j] = 0.0f;

    for (int k0 = 0; k0 < K; k0 += BK) {
        __syncthreads();
        // load A tile: 128 rows x 16 cols = 512 float4; 2 per thread
        #pragma unroll
        for (int s = 0; s < 2; s++) {
            int id = tid + s * 256;
            int ar = id / 4;              // 0..127
            int ac = (id % 4) * 4;        // 0,4,8,12
            float4 f = *reinterpret_cast<const float4*>(
                &x[(size_t)(rowBase + ar) * K + k0 + ac]);
            As[(ac + 0) * BM + ar] = f.x;
            As[(ac + 1) * BM + ar] = f.y;
            As[(ac + 2) * BM + ar] = f.z;
            As[(ac + 3) * BM + ar] = f.w;
        }
        // load B tile: 16 rows x 128 cols = 512 float4; 2 per thread
        #pragma unroll
        for (int s = 0; s < 2; s++) {
            int id = tid + s * 256;
            int br = id / 32;             // 0..15
            int bc = (id % 32) * 4;       // 0..124
            float4 f = *reinterpret_cast<const float4*>(
                &g_wt[(size_t)(k0 + br) * 256 + colBase + bc]);
            *reinterpret_cast<float4*>(&Bs[br * BN + bc]) = f;
        }
        __syncthreads();

        #pragma unroll
        for (int kk = 0; kk < BK; kk++) {
            float a[8], b[8];
            float4 a0 = *reinterpret_cast<const float4*>(&As[kk * BM + ty * 4]);
            float4 a1 = *reinterpret_cast<const float4*>(&As[kk * BM + 64 + ty * 4]);
            float4 b0 = *reinterpret_cast<const float4*>(&Bs[kk * BN + tx * 4]);
            float4 b1 = *reinterpret_cast<const float4*>(&Bs[kk * BN + 64 + tx * 4]);
            a[0]=a0.x; a[1]=a0.y; a[2]=a0.z; a[3]=a0.w;
            a[4]=a1.x; a[5]=a1.y; a[6]=a1.z; a[7]=a1.w;
            b[0]=b0.x; b[1]=b0.y; b[2]=b0.z; b[3]=b0.w;
            b[4]=b1.x; b[5]=b1.y; b[6]=b1.z; b[7]=b1.w;
            #pragma unroll
            for (int i = 0; i < 8; i++)
                #pragma unroll
                for (int j = 0; j < 8; j++)
                    acc[i][j] += a[i] * b[j];
        }
    }

    // ------- epilogue: stage sign bytes in smem, then pack 32->u32 -------
    __syncthreads();                       // everyone done reading As/Bs
    char* sb = reinterpret_cast<char*>(smem);   // 128x128 bytes = 16 KB
    #pragma unroll
    for (int i = 0; i < 8; i++) {
        int r = (i < 4) ? (ty * 4 + i) : (64 + ty * 4 + (i - 4));
        #pragma unroll
        for (int j = 0; j < 8; j++) {
            int c = (j < 4) ? (tx * 4 + j) : (64 + tx * 4 + (j - 4));
            sb[r * 128 + c] = (acc[i][j] >= 0.0f) ? 1 : 0;
        }
    }
    __syncthreads();

    // 512 words (128 rows x 4 words), 2 per thread
    #pragma unroll
    for (int s = 0; s < 2; s++) {
        int wid = tid + s * 256;
        int r = wid / 4;
        int w = wid % 4;
        unsigned v = 0;
        #pragma unroll
        for (int b = 0; b < 32; b++)
            v |= sb[r * 128 + w * 32 + b] ? (1u << b) : 0u;
        g_h1[(size_t)(rowBase + r) * 8 + blockIdx.y * 4 + w] = v;
    }
}

// ---------------- layers 2-4: fused XNOR-popcount, one warp per row ------------
__global__ __launch_bounds__(256) void l234(float* __restrict__ out, int M) {
    __shared__ unsigned sw2[1024];
    __shared__ unsigned sw3[128];
    __shared__ unsigned sw4[10];
    int tid = threadIdx.x;
    for (int i = tid; i < 1024; i += 256) sw2[i] = g_w2p[i];
    if (tid < 128) sw3[tid] = g_w3p[tid];
    if (tid < 10)  sw4[tid] = g_w4p[tid];
    __syncthreads();

    int warp = (blockIdx.x * 256 + tid) >> 5;
    int lane = tid & 31;
    if (warp >= M) return;

    unsigned a[8];
    #pragma unroll
    for (int w = 0; w < 8; w++) a[w] = g_h1[(size_t)warp * 8 + w];

    // layer 2: 128 outputs, 4 per lane (output j = q*32 + lane)
    unsigned h2w[4];
    #pragma unroll
    for (int q = 0; q < 4; q++) {
        int j = q * 32 + lane;
        int p = 0;
        #pragma unroll
        for (int w = 0; w < 8; w++) p += __popc(a[w] ^ sw2[j * 8 + w]);
        h2w[q] = __ballot_sync(0xffffffffu, (256 - 2 * p) >= 0);
    }

    // layer 3: 32 outputs, one per lane
    int p3 = 0;
    #pragma unroll
    for (int w = 0; w < 4; w++) p3 += __popc(h2w[w] ^ sw3[lane * 4 + w]);
    unsigned h3 = __ballot_sync(0xffffffffu, (128 - 2 * p3) >= 0);

    // layer 4: 10 outputs (no final sign) — exact integers in fp32
    if (lane < 10)
        out[(size_t)warp * 10 + lane] = (float)(32 - 2 * __popc(h3 ^ sw4[lane]));
}

// ---------------- launch ------------------------------------------------------
extern "C" void kernel_launch(void* const* d_in, const int* in_sizes, int n_in,
                              void* d_out, int out_size) {
    const float* x  = (const float*)d_in[0];
    const float* w1 = (const float*)d_in[1];
    const float* w2 = (const float*)d_in[2];
    const float* w3 = (const float*)d_in[3];
    const float* w4 = (const float*)d_in[4];
    int M = in_sizes[0] / 784;             // 65536

    prep_w1t<<<(784 * 256 + 255) / 256, 256>>>(w1);
    pack_w<<<5, 256>>>(w2, w3, w4);

    dim3 grid(M / 128, 2);
    l1_gemm<<<grid, 256>>>(x, M);

    l234<<<(M + 7) / 8, 256>>>((float*)d_out, M);
}

// round 4
// speedup vs baseline: 1.8648x; 1.8648x over previous
#include <cuda_runtime.h>
#include <cuda_fp16.h>
#include <cstdint>

// ---------------- device scratch (no allocation allowed) ----------------------
__device__ unsigned g_h1[65536 * 8];      // packed layer-1 sign bits [row][8]
__device__ __half   g_w1h[256 * 784];     // sign(w1) as fp16 +-1, [n][k]
__device__ unsigned g_w2t[8 * 128];       // packed sign(w2), transposed [word][j]
__device__ unsigned g_w3t[4 * 32];        // packed sign(w3), transposed [word][n]
__device__ unsigned g_w4p[16];            // packed sign(w4) rows

// ---------------- PTX helpers (base sm_103-legal only) -------------------------
__device__ __forceinline__ uint32_t smem_u32(const void* p) {
    uint32_t a;
    asm("{ .reg .u64 t; cvta.to.shared.u64 t, %1; cvt.u32.u64 %0, t; }" : "=r"(a) : "l"(p));
    return a;
}
#define LDSM4(r, addr)                                                          \
    asm volatile("ldmatrix.sync.aligned.m8n8.x4.shared.b16 {%0,%1,%2,%3}, [%4];"\
        : "=r"((r)[0]), "=r"((r)[1]), "=r"((r)[2]), "=r"((r)[3]) : "r"(addr))
#define MMA16816(d, a, b0, b1)                                                  \
    asm volatile("mma.sync.aligned.m16n8k16.row.col.f32.f16.f16.f32 "           \
        "{%0,%1,%2,%3}, {%4,%5,%6,%7}, {%8,%9}, {%0,%1,%2,%3};"                 \
        : "+f"((d)[0]), "+f"((d)[1]), "+f"((d)[2]), "+f"((d)[3])                \
        : "r"((a)[0]), "r"((a)[1]), "r"((a)[2]), "r"((a)[3]), "r"(b0), "r"(b1))
#define CP16(dst, src)                                                          \
    asm volatile("cp.async.cg.shared.global [%0], [%1], 16;" :: "r"(dst), "l"(src))
#define CP_COMMIT() asm volatile("cp.async.commit_group;" ::: "memory")
#define CP_WAIT0()  asm volatile("cp.async.wait_group 0;" ::: "memory")

// ---------------- borderline oracle: EXACT round-1 arithmetic ------------------
// Sequential fp32 FFMA chain over k ascending; empirically matches the
// reference's computed signs (round-1 kernel passed with rel_err == 0.0).
__device__ __noinline__ float seqdot(const float* __restrict__ x,
                                     const float* __restrict__ w1,
                                     int r, int n) {
    const float* xr = x  + (size_t)r * 784;
    const float* wr = w1 + (size_t)n * 784;
    float s = 0.0f;
    #pragma unroll 4
    for (int k = 0; k < 784; k++) {
        float w = (wr[k] >= 0.0f) ? 1.0f : -1.0f;
        s = fmaf(xr[k], w, s);
    }
    return s;
}

// ---------------- prep: sign(w1) -> fp16 +-1 -----------------------------------
__global__ void prep_w1h(const float* __restrict__ w1) {
    int i = blockIdx.x * blockDim.x + threadIdx.x;
    if (i < 256 * 784)
        g_w1h[i] = __float2half_rn((w1[i] >= 0.0f) ? 1.0f : -1.0f);
}

// ---------------- prep: bit-pack w2/w3/w4 (transposed layouts) -----------------
__global__ void pack_w(const float* __restrict__ w2,
                       const float* __restrict__ w3,
                       const float* __restrict__ w4) {
    int t = blockIdx.x * blockDim.x + threadIdx.x;
    if (t < 1024) {                          // w2t[w][j]
        int w = t / 128, j = t % 128;
        unsigned v = 0;
        #pragma unroll
        for (int b = 0; b < 32; b++)
            v |= (w2[j * 256 + w * 32 + b] >= 0.0f) ? (1u << b) : 0u;
        g_w2t[t] = v;
    } else if (t < 1024 + 128) {             // w3t[w][n]
        int u = t - 1024;
        int w = u / 32, n = u % 32;
        unsigned v = 0;
        #pragma unroll
        for (int b = 0; b < 32; b++)
            v |= (w3[n * 128 + w * 32 + b] >= 0.0f) ? (1u << b) : 0u;
        g_w3t[u] = v;
    } else if (t < 1024 + 128 + 10) {        // w4
        int r = t - 1152;
        unsigned v = 0;
        #pragma unroll
        for (int b = 0; b < 32; b++)
            v |= (w4[r * 32 + b] >= 0.0f) ? (1u << b) : 0u;
        g_w4p[r] = v;
    }
}

// ---------------- layer 1: HMMA fp16-split GEMM + oracle sign epilogue ---------
// CTA tile 64(M) x 256(N); K = 7 chunks of 112. Warp tile 32x64 (2x4 warps).
// smem per stage: Ahi[64][120]h (15360) | Alo (15360) | B[256][120]h (61440)
static constexpr int STAGE = 92160;
static constexpr int SMEM_TOTAL = 2 * STAGE;   // 184320

__global__ __launch_bounds__(256, 1) void l1_gemm(const float* __restrict__ x,
                                                  const float* __restrict__ w1) {
    extern __shared__ char smem[];
    const uint32_t sbase = smem_u32(smem);
    const int tid  = threadIdx.x;
    const int lane = tid & 31;
    const int wid  = tid >> 5;
    const int wm   = wid & 1;          // M half (rows 32*wm..)
    const int wn   = wid >> 1;         // N block of 64
    const int rowBase = blockIdx.x * 64;

    float acc[2][8][4];
    #pragma unroll
    for (int mi = 0; mi < 2; mi++)
        #pragma unroll
        for (int nf = 0; nf < 8; nf++)
            #pragma unroll
            for (int q = 0; q < 4; q++) acc[mi][nf][q] = 0.0f;

    // ldmatrix per-thread offsets
    const uint32_t aoff = (uint32_t)((lane & 15) * 240 + (lane >> 4) * 16 + wm * 7680);
    const uint32_t boff = (uint32_t)(((lane & 7) + ((lane >> 4) & 1) * 8) * 240
                                     + ((lane >> 3) & 1) * 16 + wn * 15360);

    float4 fr[7];

    auto ldgA = [&](int c) {
        #pragma unroll
        for (int i = 0; i < 7; i++) {
            int g = tid + 256 * i;
            int row = g / 28, c4 = g % 28;
            fr[i] = *reinterpret_cast<const float4*>(
                &x[(size_t)(rowBase + row) * 784 + c * 112 + c4 * 4]);
        }
    };
    auto stsA = [&](int buf) {
        const uint32_t sAhi = sbase + buf * STAGE;
        const uint32_t sAlo = sAhi + 15360;
        #pragma unroll
        for (int i = 0; i < 7; i++) {
            int g = tid + 256 * i;
            int row = g / 28, c4 = g % 28;
            float4 f = fr[i];
            __half2 h01 = __floats2half2_rn(f.x, f.y);
            __half2 h23 = __floats2half2_rn(f.z, f.w);
            float2 b01 = __half22float2(h01);
            float2 b23 = __half22float2(h23);
            __half2 l01 = __floats2half2_rn(f.x - b01.x, f.y - b01.y);
            __half2 l23 = __floats2half2_rn(f.z - b23.x, f.w - b23.y);
            uint32_t off = (uint32_t)(row * 240 + c4 * 8);
            uint32_t uh0 = *reinterpret_cast<uint32_t*>(&h01);
            uint32_t uh1 = *reinterpret_cast<uint32_t*>(&h23);
            uint32_t ul0 = *reinterpret_cast<uint32_t*>(&l01);
            uint32_t ul1 = *reinterpret_cast<uint32_t*>(&l23);
            asm volatile("st.shared.v2.b32 [%0], {%1,%2};" :: "r"(sAhi + off), "r"(uh0), "r"(uh1) : "memory");
            asm volatile("st.shared.v2.b32 [%0], {%1,%2};" :: "r"(sAlo + off), "r"(ul0), "r"(ul1) : "memory");
        }
    };
    auto cpB = [&](int c, int buf) {
        const uint32_t sB = sbase + buf * STAGE + 30720;
        const __half* src = &g_w1h[c * 112];
        #pragma unroll
        for (int i = 0; i < 14; i++) {
            int g = tid + 256 * i;
            int row = g / 14, c16 = g % 14;
            CP16(sB + (uint32_t)(row * 240 + c16 * 16),
                 (const void*)(src + (size_t)row * 784 + c16 * 8));
        }
    };
    auto compute = [&](int buf) {
        const uint32_t sAhi = sbase + buf * STAGE;
        const uint32_t sAlo = sAhi + 15360;
        const uint32_t sB   = sAhi + 30720;
        #pragma unroll
        for (int ks = 0; ks < 7; ks++) {
            uint32_t ah0[4], ah1[4], al0[4], al1[4], bf[4][4];
            LDSM4(ah0, sAhi + aoff + ks * 32);
            LDSM4(ah1, sAhi + aoff + 3840 + ks * 32);
            LDSM4(al0, sAlo + aoff + ks * 32);
            LDSM4(al1, sAlo + aoff + 3840 + ks * 32);
            #pragma unroll
            for (int nbp = 0; nbp < 4; nbp++)
                LDSM4(bf[nbp], sB + boff + nbp * 3840 + ks * 32);
            #pragma unroll
            for (int nf = 0; nf < 8; nf++) {
                uint32_t b0 = bf[nf >> 1][(nf & 1) * 2];
                uint32_t b1 = bf[nf >> 1][(nf & 1) * 2 + 1];
                MMA16816(acc[0][nf], ah0, b0, b1);
                MMA16816(acc[1][nf], ah1, b0, b1);
                MMA16816(acc[0][nf], al0, b0, b1);
                MMA16816(acc[1][nf], al1, b0, b1);
            }
        }
    };

    // ---- prologue: chunk 0 ----
    ldgA(0);
    cpB(0, 0);
    CP_COMMIT();
    stsA(0);
    CP_WAIT0();
    __syncthreads();

    // ---- main loop ----
    for (int c = 0; c < 7; c++) {
        int cur = c & 1;
        if (c < 6) { ldgA(c + 1); cpB(c + 1, cur ^ 1); CP_COMMIT(); }
        compute(cur);
        if (c < 6) { stsA(cur ^ 1); CP_WAIT0(); __syncthreads(); }
    }

    // ---- epilogue: oracle-corrected sign bytes -> smem -> packed words ----
    __syncthreads();                        // all compute done; reuse smem
    char* sb = smem;                        // 64 x 256 bytes
    #pragma unroll
    for (int mi = 0; mi < 2; mi++) {
        #pragma unroll
        for (int nf = 0; nf < 8; nf++) {
            #pragma unroll
            for (int q = 0; q < 4; q++) {
                float v = acc[mi][nf][q];
                int rl = wm * 32 + mi * 16 + (lane >> 2) + ((q >> 1) << 3);
                int cc = wn * 64 + nf * 8 + (lane & 3) * 2 + (q & 1);
                if (fabsf(v) < 1e-3f)       // borderline: use reference-order dot
                    v = seqdot(x, w1, rowBase + rl, cc);
                sb[rl * 256 + cc] = (v >= 0.0f) ? 1 : 0;
            }
        }
    }
    __syncthreads();

    const unsigned* sbu = reinterpret_cast<const unsigned*>(sb);
    #pragma unroll
    for (int s = 0; s < 2; s++) {
        int q = tid + s * 256;              // 512 words
        int r = q >> 3, w = q & 7;
        unsigned v = 0;
        #pragma unroll
        for (int j = 0; j < 8; j++) {
            unsigned u = sbu[r * 64 + w * 8 + j];
            v |= (((u & 0x01010101u) * 0x01020408u) >> 24) << (j * 4);
        }
        g_h1[(size_t)(rowBase + r) * 8 + w] = v;
    }
}

// ---------------- layers 2-4: XNOR-popcount, conflict-free smem ----------------
__global__ __launch_bounds__(256) void l234(float* __restrict__ out, int M) {
    __shared__ unsigned sw2[1024];   // [w][j]
    __shared__ unsigned sw3[128];    // [w][n]
    __shared__ unsigned sw4[10];
    int tid = threadIdx.x;
    for (int i = tid; i < 1024; i += 256) sw2[i] = g_w2t[i];
    if (tid < 128) sw3[tid] = g_w3t[tid];
    if (tid < 10)  sw4[tid] = g_w4p[tid];
    __syncthreads();

    int warp = (blockIdx.x * 256 + tid) >> 5;
    int lane = tid & 31;
    if (warp >= M) return;

    unsigned a[8];
    uint4 a0 = *reinterpret_cast<const uint4*>(&g_h1[(size_t)warp * 8]);
    uint4 a1 = *reinterpret_cast<const uint4*>(&g_h1[(size_t)warp * 8 + 4]);
    a[0]=a0.x; a[1]=a0.y; a[2]=a0.z; a[3]=a0.w;
    a[4]=a1.x; a[5]=a1.y; a[6]=a1.z; a[7]=a1.w;

    unsigned h2w[4];
    #pragma unroll
    for (int q = 0; q < 4; q++) {
        int j = q * 32 + lane;
        int p = 0;
        #pragma unroll
        for (int w = 0; w < 8; w++) p += __popc(a[w] ^ sw2[w * 128 + j]);
        h2w[q] = __ballot_sync(0xffffffffu, (256 - 2 * p) >= 0);
    }

    int p3 = 0;
    #pragma unroll
    for (int w = 0; w < 4; w++) p3 += __popc(h2w[w] ^ sw3[w * 32 + lane]);
    unsigned h3 = __ballot_sync(0xffffffffu, (128 - 2 * p3) >= 0);

    if (lane < 10)
        out[(size_t)warp * 10 + lane] = (float)(32 - 2 * __popc(h3 ^ sw4[lane]));
}

// ---------------- launch ------------------------------------------------------
extern "C" void kernel_launch(void* const* d_in, const int* in_sizes, int n_in,
                              void* d_out, int out_size) {
    const float* x  = (const float*)d_in[0];
    const float* w1 = (const float*)d_in[1];
    const float* w2 = (const float*)d_in[2];
    const float* w3 = (const float*)d_in[3];
    const float* w4 = (const float*)d_in[4];
    int M = in_sizes[0] / 784;             // 65536

    cudaFuncSetAttribute(l1_gemm, cudaFuncAttributeMaxDynamicSharedMemorySize, SMEM_TOTAL);

    prep_w1h<<<(256 * 784 + 255) / 256, 256>>>(w1);
    pack_w<<<5, 256>>>(w2, w3, w4);
    l1_gemm<<<M / 64, 256, SMEM_TOTAL>>>(x, w1);
    l234<<<(M + 7) / 8, 256>>>((float*)d_out, M);
}